// round 1
// baseline (speedup 1.0000x reference)
#include <cuda_runtime.h>
#include <math.h>

// Problem constants (fixed by the dataset)
#define NB        16384          // number of 3x3 blocks
#define BDIM      (3 * NB)       // 49152 floats per row of x
#define BATCH     4096

#define THREADS            256
#define BLOCKS_PER_THREAD  8                     // 24 floats of x per thread per row
#define BLOCKS_PER_CTA     (THREADS * BLOCKS_PER_THREAD)   // 2048
#define COL_TILES          (NB / BLOCKS_PER_CTA)           // 8
#define ROWS_PER_CTA       16
#define ROW_GROUPS         (BATCH / ROWS_PER_CTA)          // 256

// Packed symmetric W per block: (W00, W01, W02, W11, W12, W22)
__device__ float g_W[NB * 6];

__global__ void zero_kernel(float* __restrict__ out, int n) {
    int i = blockIdx.x * blockDim.x + threadIdx.x;
    if (i < n) out[i] = 0.0f;
}

__device__ __forceinline__ float softplus_f(float v) {
    // matches jax.nn.softplus to fp32 precision; guard overflow
    return (v > 20.0f) ? v : log1pf(expf(v));
}

__global__ void build_w_kernel(const float* __restrict__ w) {
    int n = blockIdx.x * blockDim.x + threadIdx.x;
    if (n >= NB) return;
    float w0 = w[n * 6 + 0];
    float w1 = w[n * 6 + 1];
    float w2 = w[n * 6 + 2];
    float w3 = w[n * 6 + 3];
    float w4 = w[n * 6 + 4];
    float w5 = w[n * 6 + 5];

    float a = softplus_f(w0);   // M[0][0]
    float b = w1;               // M[0][1]
    float c = w2;               // M[0][2]
    float d = softplus_f(w3);   // M[1][1]
    float e = w4;               // M[1][2]
    float f = softplus_f(w5);   // M[2][2]

    // W = M^T M (symmetric)
    g_W[n * 6 + 0] = a * a;                  // W00
    g_W[n * 6 + 1] = a * b;                  // W01
    g_W[n * 6 + 2] = a * c;                  // W02
    g_W[n * 6 + 3] = b * b + d * d;          // W11
    g_W[n * 6 + 4] = b * c + d * e;          // W12
    g_W[n * 6 + 5] = c * c + e * e + f * f;  // W22
}

__global__ void __launch_bounds__(THREADS, 2)
main_kernel(const float* __restrict__ x, float* __restrict__ out) {
    const int t    = threadIdx.x;
    const int tile = blockIdx.x;
    const int row0 = blockIdx.y * ROWS_PER_CTA;

    const int nb0   = tile * BLOCKS_PER_CTA + t * BLOCKS_PER_THREAD; // first block owned
    const int colf0 = nb0 * 3;                                       // float offset within a row

    // W for this thread's 8 blocks -> 48 registers, reused across ROWS_PER_CTA rows
    float w[BLOCKS_PER_THREAD * 6];
    {
        const float4* wp = reinterpret_cast<const float4*>(g_W + (size_t)nb0 * 6);
        #pragma unroll
        for (int i = 0; i < (BLOCKS_PER_THREAD * 6) / 4; ++i) {
            float4 v = wp[i];
            w[4 * i + 0] = v.x; w[4 * i + 1] = v.y;
            w[4 * i + 2] = v.z; w[4 * i + 3] = v.w;
        }
    }

    __shared__ float sacc[3];

    for (int r = 0; r < ROWS_PER_CTA; ++r) {
        const int row = row0 + r;
        if (t < 3) sacc[t] = 0.0f;
        __syncthreads();

        // 24 consecutive floats of this row: 6x LDG.128
        const float4* xp = reinterpret_cast<const float4*>(
            x + (size_t)row * BDIM + colf0);
        float xv[BLOCKS_PER_THREAD * 3];
        #pragma unroll
        for (int i = 0; i < (BLOCKS_PER_THREAD * 3) / 4; ++i) {
            float4 v = xp[i];
            xv[4 * i + 0] = v.x; xv[4 * i + 1] = v.y;
            xv[4 * i + 2] = v.z; xv[4 * i + 3] = v.w;
        }

        float s0 = 0.0f, s1 = 0.0f, s2 = 0.0f;
        #pragma unroll
        for (int j = 0; j < BLOCKS_PER_THREAD; ++j) {
            float x0 = xv[3 * j + 0], x1 = xv[3 * j + 1], x2 = xv[3 * j + 2];
            float w00 = w[6 * j + 0], w01 = w[6 * j + 1], w02 = w[6 * j + 2];
            float w11 = w[6 * j + 3], w12 = w[6 * j + 4], w22 = w[6 * j + 5];
            s0 = fmaf(w00, x0, fmaf(w01, x1, fmaf(w02, x2, s0)));
            s1 = fmaf(w01, x0, fmaf(w11, x1, fmaf(w12, x2, s1)));
            s2 = fmaf(w02, x0, fmaf(w12, x1, fmaf(w22, x2, s2)));
        }

        // warp tree-reduce
        #pragma unroll
        for (int off = 16; off; off >>= 1) {
            s0 += __shfl_down_sync(0xffffffffu, s0, off);
            s1 += __shfl_down_sync(0xffffffffu, s1, off);
            s2 += __shfl_down_sync(0xffffffffu, s2, off);
        }
        if ((t & 31) == 0) {
            atomicAdd(&sacc[0], s0);
            atomicAdd(&sacc[1], s1);
            atomicAdd(&sacc[2], s2);
        }
        __syncthreads();
        if (t < 3) atomicAdd(&out[row * 3 + t], sacc[t]);
    }
}

extern "C" void kernel_launch(void* const* d_in, const int* in_sizes, int n_in,
                              void* d_out, int out_size) {
    const float* x      = (const float*)d_in[0];   // [4096, 49152] f32
    const float* weight = (const float*)d_in[1];   // [16384, 6]    f32
    float* out          = (float*)d_out;           // [4096, 3]     f32

    // 1) zero the (poisoned) output since we accumulate with atomics
    zero_kernel<<<(out_size + 255) / 256, 256>>>(out, out_size);

    // 2) expand weight -> packed symmetric 3x3 blocks
    build_w_kernel<<<(NB + 255) / 256, 256>>>(weight);

    // 3) streaming blocked reduction
    dim3 grid(COL_TILES, ROW_GROUPS);
    main_kernel<<<grid, THREADS>>>(x, out);
}

// round 3
// speedup vs baseline: 1.2152x; 1.2152x over previous
#include <cuda_runtime.h>
#include <math.h>
#include <stdint.h>

// Problem constants (fixed by the dataset)
#define NB        16384          // number of 3x3 blocks
#define BDIM      (3 * NB)       // 49152 floats per row of x
#define BATCH     4096

#define THREADS            256
#define BPT                8                     // blocks per thread
#define BLOCKS_PER_CTA     (THREADS * BPT)       // 2048
#define FLOATS_PER_CTA     (BLOCKS_PER_CTA * 3)  // 6144 floats = 24KB per row-chunk
#define F4_PER_CTA         (FLOATS_PER_CTA / 4)  // 1536
#define F4_PER_THREAD      (F4_PER_CTA / THREADS)// 6
#define COL_TILES          (NB / BLOCKS_PER_CTA) // 8
#define ROWS_PER_CTA       16
#define ROW_GROUPS         (BATCH / ROWS_PER_CTA)// 256

// Per-thread smem slot: 24 data floats + 4 pad = 28 floats (112B).
// 112B thread stride => in each 8-lane LDS.128 phase, banks 28t mod 32 are distinct.
#define SLOT_F   28
#define BUF_F    (THREADS * SLOT_F)   // 7168 floats = 28672 B per buffer
#define NBUF     3
#define SMEM_BYTES (NBUF * BUF_F * 4) // 86016 B (dynamic)

// Packed symmetric W per block: (W00, W01, W02, W11, W12, W22)
__device__ float g_W[NB * 6];

__device__ __forceinline__ float softplus_f(float v) {
    return (v > 20.0f) ? v : log1pf(expf(v));
}

// Builds packed W AND zeroes the (poisoned) output buffer.
__global__ void build_w_kernel(const float* __restrict__ w, float* __restrict__ out,
                               int out_n) {
    int n = blockIdx.x * blockDim.x + threadIdx.x;
    if (n < out_n) out[n] = 0.0f;
    if (n >= NB) return;
    float w0 = w[n * 6 + 0], w1 = w[n * 6 + 1], w2 = w[n * 6 + 2];
    float w3 = w[n * 6 + 3], w4 = w[n * 6 + 4], w5 = w[n * 6 + 5];

    float a = softplus_f(w0);   // M00
    float b = w1, c = w2;       // M01, M02
    float d = softplus_f(w3);   // M11
    float e = w4;               // M12
    float f = softplus_f(w5);   // M22

    g_W[n * 6 + 0] = a * a;
    g_W[n * 6 + 1] = a * b;
    g_W[n * 6 + 2] = a * c;
    g_W[n * 6 + 3] = b * b + d * d;
    g_W[n * 6 + 4] = b * c + d * e;
    g_W[n * 6 + 5] = c * c + e * e + f * f;
}

__device__ __forceinline__ void cp_async16(uint32_t dst, const void* src) {
    asm volatile("cp.async.cg.shared.global [%0], [%1], 16;\n" :: "r"(dst), "l"(src));
}
__device__ __forceinline__ void cp_commit() {
    asm volatile("cp.async.commit_group;\n");
}
template <int N>
__device__ __forceinline__ void cp_wait() {
    asm volatile("cp.async.wait_group %0;\n" :: "n"(N));
}

extern __shared__ float sbuf[];

__global__ void __launch_bounds__(THREADS, 2)
main_kernel(const float* __restrict__ x, float* __restrict__ out) {
    const int t    = threadIdx.x;
    const int lane = t & 31;
    const int tile = blockIdx.x;
    const int row0 = blockIdx.y * ROWS_PER_CTA;

    const int nb0 = tile * BLOCKS_PER_CTA + t * BPT;   // first block this thread owns

    // ---- W for this thread's 8 blocks -> 48 regs, reused across 16 rows ----
    float w[BPT * 6];
    {
        const float4* wp = reinterpret_cast<const float4*>(g_W + (size_t)nb0 * 6);
        #pragma unroll
        for (int i = 0; i < (BPT * 6) / 4; ++i) {
            float4 v = wp[i];
            w[4 * i + 0] = v.x; w[4 * i + 1] = v.y;
            w[4 * i + 2] = v.z; w[4 * i + 3] = v.w;
        }
    }

    // ---- cp.async destination offsets (constant across rows) ----
    // global float4 index g within the CTA chunk -> owner thread g/6, sub g%6
    uint32_t sbase = (uint32_t)__cvta_generic_to_shared(sbuf);
    uint32_t dstoff[F4_PER_THREAD];
    #pragma unroll
    for (int i = 0; i < F4_PER_THREAD; ++i) {
        int g     = t + THREADS * i;
        int owner = g / 6;
        int sub   = g - owner * 6;
        dstoff[i] = (uint32_t)(owner * (SLOT_F * 4) + sub * 16);
    }

    const float4* gbase = reinterpret_cast<const float4*>(x) +
                          (size_t)row0 * (BDIM / 4) + (size_t)tile * F4_PER_CTA;

    // issue the coalesced async copy of one row-chunk into buffer b
    auto issue_row = [&](int r, int b) {
        const float4* src = gbase + (size_t)r * (BDIM / 4);
        uint32_t dbase = sbase + (uint32_t)(b * BUF_F * 4);
        #pragma unroll
        for (int i = 0; i < F4_PER_THREAD; ++i)
            cp_async16(dbase + dstoff[i], src + (t + THREADS * i));
        cp_commit();
    };

    // ---- 3-stage pipeline, one barrier per row ----
    // Invariant at iter r: groups for rows 0..r+1 have been issued.
    issue_row(0, 0);
    issue_row(1, 1);

    for (int r = 0; r < ROWS_PER_CTA; ++r) {
        // 1) row r's data landed (this thread's view); row r+1 may be pending
        if (r + 1 < ROWS_PER_CTA) cp_wait<1>();
        else                      cp_wait<0>();
        // 2) buffer r%3 now CTA-visible; all reads of buffer (r-1)%3 (iter r-1
        //    compute) are complete on every thread
        __syncthreads();
        // 3) safe to overwrite buffer (r+2)%3 == (r-1)%3
        if (r + 2 < ROWS_PER_CTA) issue_row(r + 2, (r + 2) % NBUF);

        // 4) compute row r: 24 floats via 6x LDS.128 (conflict-free phases)
        const float4* sb = reinterpret_cast<const float4*>(
            sbuf + (size_t)(r % NBUF) * BUF_F + (size_t)t * SLOT_F);
        float xv[BPT * 3];
        #pragma unroll
        for (int i = 0; i < F4_PER_THREAD; ++i) {
            float4 v = sb[i];
            xv[4 * i + 0] = v.x; xv[4 * i + 1] = v.y;
            xv[4 * i + 2] = v.z; xv[4 * i + 3] = v.w;
        }

        float s0 = 0.0f, s1 = 0.0f, s2 = 0.0f;
        #pragma unroll
        for (int j = 0; j < BPT; ++j) {
            float x0 = xv[3 * j + 0], x1 = xv[3 * j + 1], x2 = xv[3 * j + 2];
            float w00 = w[6 * j + 0], w01 = w[6 * j + 1], w02 = w[6 * j + 2];
            float w11 = w[6 * j + 3], w12 = w[6 * j + 4], w22 = w[6 * j + 5];
            s0 = fmaf(w00, x0, fmaf(w01, x1, fmaf(w02, x2, s0)));
            s1 = fmaf(w01, x0, fmaf(w11, x1, fmaf(w12, x2, s1)));
            s2 = fmaf(w02, x0, fmaf(w12, x1, fmaf(w22, x2, s2)));
        }

        // warp tree-reduce, lane 0 -> global RED
        #pragma unroll
        for (int off = 16; off; off >>= 1) {
            s0 += __shfl_down_sync(0xffffffffu, s0, off);
            s1 += __shfl_down_sync(0xffffffffu, s1, off);
            s2 += __shfl_down_sync(0xffffffffu, s2, off);
        }
        if (lane == 0) {
            const int row = row0 + r;
            atomicAdd(&out[row * 3 + 0], s0);
            atomicAdd(&out[row * 3 + 1], s1);
            atomicAdd(&out[row * 3 + 2], s2);
        }
    }
}

extern "C" void kernel_launch(void* const* d_in, const int* in_sizes, int n_in,
                              void* d_out, int out_size) {
    const float* x      = (const float*)d_in[0];   // [4096, 49152] f32
    const float* weight = (const float*)d_in[1];   // [16384, 6]    f32
    float* out          = (float*)d_out;           // [4096, 3]     f32

    // dynamic smem > 48KB needs an attribute bump (idempotent, capture-safe)
    static_assert(SMEM_BYTES == 86016, "smem layout");
    cudaFuncSetAttribute(main_kernel, cudaFuncAttributeMaxDynamicSharedMemorySize,
                         SMEM_BYTES);

    // 1) build packed W + zero the poisoned output (atomics accumulate into it)
    build_w_kernel<<<(NB + 255) / 256, 256>>>(weight, out, out_size);

    // 2) streaming blocked reduction
    dim3 grid(COL_TILES, ROW_GROUPS);
    main_kernel<<<grid, THREADS, SMEM_BYTES>>>(x, out);
}